// round 1
// baseline (speedup 1.0000x reference)
#include <cuda_runtime.h>

// LSTMPredictor: B=1024, T=512, I=4, H=128 (4H=512 gates), O=4.
// Persistent-CTA fp32 LSTM: 128 CTAs x 256 threads, each CTA owns 8 batch rows
// for all 512 timesteps. W_hh streamed from L1/L2 (pre-transposed), h/c on-chip.

#define B_SZ    1024
#define T_SZ    512
#define I_SZ    4
#define H_SZ    128
#define G_SZ    512           // 4*H
#define NB      8             // batch rows per CTA
#define CTAS    (B_SZ / NB)   // 128
#define THREADS 256

// ---------------- device scratch (allocation-free) ----------------
__device__ __align__(16) float g_Wt[H_SZ * G_SZ];   // Wt[k][g] = W_hh[g][k]
__device__ float g_bias[G_SZ];                      // b_ih + b_hh

// ---------------- prep: transpose W_hh, fuse biases ----------------
__global__ void prep_kernel(const float* __restrict__ W_hh,
                            const float* __restrict__ b_ih,
                            const float* __restrict__ b_hh)
{
    int idx = blockIdx.x * blockDim.x + threadIdx.x;
    if (idx < H_SZ * G_SZ) {
        int k = idx >> 9;        // / 512
        int g = idx & 511;
        g_Wt[idx] = W_hh[g * H_SZ + k];
    }
    if (idx < G_SZ) g_bias[idx] = b_ih[idx] + b_hh[idx];
}

// ---------------- activations (overflow-safe, MUFU-based) ----------------
__device__ __forceinline__ float sigf(float x) {
    // 1/(1+e^-x): x->-inf gives 1/inf = 0, x->+inf gives 1. Safe.
    return __fdividef(1.0f, 1.0f + __expf(-x));
}
__device__ __forceinline__ float tanhf_fast(float x) {
    // 1 - 2/(e^{2x}+1): x->+inf -> 1, x->-inf -> -1. No inf/inf NaN.
    return 1.0f - __fdividef(2.0f, __expf(2.0f * x) + 1.0f);
}

// smem layout (floats):
//   part [2][NB][512] : 8192    @ 0       k-split partial gate sums
//   h_buf[128][NB]    : 1024    @ 8192    hidden state, k-major
//   wih  [512][4]     : 2048    @ 9216    W_ih
//   bias [512]        :  512    @ 11264
//   xs   [NB][4]      :   32    @ 11776   x[b][t][:] for current step
#define SM_PART  0
#define SM_H     8192
#define SM_WIH   9216
#define SM_BIAS  11264
#define SM_XS    11776
#define SM_TOTAL 11808          // 47232 bytes < 48KB static limit

__global__ __launch_bounds__(THREADS)
void lstm_kernel(const float* __restrict__ x,
                 const float* __restrict__ W_ih,
                 const float* __restrict__ W_fc,
                 const float* __restrict__ b_fc,
                 float* __restrict__ out)
{
    __shared__ __align__(16) float sm[SM_TOTAL];
    float* part  = sm + SM_PART;
    float* h_buf = sm + SM_H;
    float* wih   = sm + SM_WIH;
    float* biass = sm + SM_BIAS;
    float* xs    = sm + SM_XS;

    const int t  = threadIdx.x;
    const int ks = t >> 7;        // k-half: 0 or 1 (64 k each)
    const int gt = t & 127;       // gate-quad: gates [4*gt, 4*gt+4)
    const int bb = blockIdx.x * NB;

    // epilogue mapping: hidden unit j, batch half
    const int j    = t & 127;
    const int half = t >> 7;

    // ---- one-time init ----
    for (int i = t; i < G_SZ * I_SZ; i += THREADS) wih[i]   = W_ih[i];
    for (int i = t; i < G_SZ;        i += THREADS) biass[i] = g_bias[i];
    for (int i = t; i < H_SZ * NB;   i += THREADS) h_buf[i] = 0.0f;

    float creg[4];
#pragma unroll
    for (int bi = 0; bi < 4; ++bi) creg[bi] = 0.0f;

    const float4* Wt4 = reinterpret_cast<const float4*>(g_Wt);
    const float4* hs4 = reinterpret_cast<const float4*>(h_buf);
    const float4* x4  = reinterpret_cast<const float4*>(x);
    float4* part4     = reinterpret_cast<float4*>(part);
    float4* xs4       = reinterpret_cast<float4*>(xs);

    __syncthreads();

    const int kbase = ks * 64;

    for (int step = 0; step < T_SZ; ++step) {
        // prefetch x[b][step][0:4] (16B per row); consumed after barrier
        if (t < NB) {
            xs4[t] = x4[(bb + t) * T_SZ + step];
        }

        // ---- recurrent GEMM: partial gates for 4 gates x 8 batch ----
        float acc[NB][4];
#pragma unroll
        for (int b = 0; b < NB; ++b)
#pragma unroll
            for (int gi = 0; gi < 4; ++gi) acc[b][gi] = 0.0f;

#pragma unroll 8
        for (int kk = 0; kk < 64; ++kk) {
            const int k = kbase + kk;
            const float4 w  = Wt4[k * (G_SZ / 4) + gt];  // gates 4*gt..+3 (coalesced)
            const float4 ha = hs4[k * 2];                // h[k][b0..3] (broadcast)
            const float4 hb = hs4[k * 2 + 1];            // h[k][b4..7]
#define ROWFMA(b, hv) \
            acc[b][0] += (hv) * w.x; acc[b][1] += (hv) * w.y; \
            acc[b][2] += (hv) * w.z; acc[b][3] += (hv) * w.w;
            ROWFMA(0, ha.x) ROWFMA(1, ha.y) ROWFMA(2, ha.z) ROWFMA(3, ha.w)
            ROWFMA(4, hb.x) ROWFMA(5, hb.y) ROWFMA(6, hb.z) ROWFMA(7, hb.w)
#undef ROWFMA
        }

        // ---- store partials: part[ks][b][g], conflict-free v4 ----
#pragma unroll
        for (int b = 0; b < NB; ++b) {
            part4[((ks * NB + b) * G_SZ) / 4 + gt] =
                make_float4(acc[b][0], acc[b][1], acc[b][2], acc[b][3]);
        }
        __syncthreads();

        // ---- epilogue: thread owns hidden j for 4 batch rows ----
#pragma unroll
        for (int bi = 0; bi < 4; ++bi) {
            const int b = half * 4 + bi;
            float pre[4];
#pragma unroll
            for (int q = 0; q < 4; ++q) {
                const int g = q * H_SZ + j;
                float s = part[(0 * NB + b) * G_SZ + g]
                        + part[(1 * NB + b) * G_SZ + g];
                s += biass[g];
                s += wih[g * 4 + 0] * xs[b * 4 + 0]
                   + wih[g * 4 + 1] * xs[b * 4 + 1]
                   + wih[g * 4 + 2] * xs[b * 4 + 2]
                   + wih[g * 4 + 3] * xs[b * 4 + 3];
                pre[q] = s;
            }
            const float ig = sigf(pre[0]);
            const float fg = sigf(pre[1]);
            const float gg = tanhf_fast(pre[2]);
            const float og = sigf(pre[3]);
            float c = fg * creg[bi] + ig * gg;
            creg[bi] = c;
            h_buf[j * NB + b] = og * tanhf_fast(c);
        }
        __syncthreads();
    }

    // ---- final FC: out[b][o] = h_T[b] . W_fc[o] + b_fc[o] ----
    if (t < NB * 4) {
        const int b = t >> 2;
        const int o = t & 3;
        float s = b_fc[o];
#pragma unroll 8
        for (int jj = 0; jj < H_SZ; ++jj)
            s += h_buf[jj * NB + b] * W_fc[o * H_SZ + jj];
        out[(bb + b) * 4 + o] = s;
    }
}

// ---------------- launch ----------------
extern "C" void kernel_launch(void* const* d_in, const int* in_sizes, int n_in,
                              void* d_out, int out_size)
{
    const float* x    = (const float*)d_in[0];
    const float* W_ih = (const float*)d_in[1];
    const float* W_hh = (const float*)d_in[2];
    const float* b_ih = (const float*)d_in[3];
    const float* b_hh = (const float*)d_in[4];
    const float* W_fc = (const float*)d_in[5];
    const float* b_fc = (const float*)d_in[6];
    float* out = (float*)d_out;

    prep_kernel<<<(H_SZ * G_SZ + 255) / 256, 256>>>(W_hh, b_ih, b_hh);
    lstm_kernel<<<CTAS, THREADS>>>(x, W_ih, W_fc, b_fc, out);
}